// round 1
// baseline (speedup 1.0000x reference)
#include <cuda_runtime.h>
#include <cuda_bf16.h>
#include <stdint.h>

// Problem constants
#define NB   32
#define CIN  256
#define COUT 256
#define H    56
#define W    56
#define HW   (H*W)          // 3136
#define NHW  (NB*HW)        // 100352
#define CW   8              // 256 bits = 8 u32 words
#define TAPS 9
#define TH   4              // output rows per conv block

// -------- device scratch (no allocations allowed) --------
__device__ uint32_t g_xb[NB*HW*CW];          // packed activations [n][h][w][8]  (3.2 MB)
__device__ uint32_t g_wb[COUT*TAPS*CW];      // packed weights     [oc][tap][8]  (72 KB)
__device__ short    g_y[NB*HW*COUT];         // conv result NHWC int16           (51 MB)
__device__ int                g_sum[COUT];
__device__ unsigned long long g_sq[COUT];
__device__ float    g_scale[COUT];
__device__ float    g_shift[COUT];

// -------- kernel 1: pack activations into bitplanes --------
__global__ void pack_x_kernel(const float* __restrict__ x) {
    int tid = blockIdx.x * blockDim.x + threadIdx.x;   // one thread per (n,h,w)
    if (tid >= NHW) return;
    int n   = tid / HW;
    int rem = tid - n * HW;                            // h*56 + w

    uint32_t wds[CW];
#pragma unroll
    for (int i = 0; i < CW; i++) wds[i] = 0u;

#pragma unroll 8
    for (int c = 0; c < CIN; c++) {
        float v = x[(size_t)(n * CIN + c) * HW + rem];
        uint32_t bit = (v > 0.0f) ? 1u : 0u;
        wds[c >> 5] |= bit << (c & 31);
    }
    uint4* dst = reinterpret_cast<uint4*>(&g_xb[(size_t)tid * CW]);
    dst[0] = make_uint4(wds[0], wds[1], wds[2], wds[3]);
    dst[1] = make_uint4(wds[4], wds[5], wds[6], wds[7]);
}

// -------- kernel 2: pack weights + zero the stat accumulators --------
__global__ void pack_w_kernel(const float* __restrict__ w) {
    int tid = blockIdx.x * blockDim.x + threadIdx.x;   // one thread per (oc,tap,word)
    if (tid < COUT) { g_sum[tid] = 0; g_sq[tid] = 0ull; }
    if (tid >= COUT * TAPS * CW) return;
    int oc   = tid / (TAPS * CW);
    int r    = tid - oc * (TAPS * CW);
    int tap  = r >> 3;
    int word = r & 7;

    uint32_t bits = 0u;
#pragma unroll
    for (int j = 0; j < 32; j++) {
        int ci = (word << 5) + j;
        float v = w[(size_t)(oc * CIN + ci) * TAPS + tap];
        bits |= (v > 0.0f ? 1u : 0u) << j;
    }
    g_wb[tid] = bits;
}

// -------- kernel 3: XNOR-popcount conv + exact integer stats --------
__global__ void __launch_bounds__(256, 2)
conv_kernel() {
    __shared__ uint32_t sx[TH + 2][W + 2][CW];         // ~10.9 KB, halo = zeros

    const int n   = blockIdx.y;
    const int oh0 = blockIdx.x * TH;
    const int oc  = threadIdx.x;                       // 1 thread = 1 output channel

    // cooperative smem load of x bit-tile (rows oh0-1 .. oh0+TH, cols -1..56)
    const int TOT = (TH + 2) * (W + 2) * CW;
    for (int i = oc; i < TOT; i += 256) {
        int wrd  = i & 7;
        int rest = i >> 3;
        int c    = rest % (W + 2);
        int r    = rest / (W + 2);
        int gh   = oh0 - 1 + r;
        int gw   = c - 1;
        uint32_t v = 0u;
        if (gh >= 0 && gh < H && gw >= 0 && gw < W)
            v = g_xb[(((size_t)n * H + gh) * W + gw) * CW + wrd];
        sx[r][c][wrd] = v;
    }

    // per-thread weights (72 regs) + per-tap padding correction Ct
    uint32_t wr[TAPS][CW];
    int      Ct[TAPS];
    {
        const uint32_t* wp = &g_wb[(size_t)oc * TAPS * CW];
#pragma unroll
        for (int t = 0; t < TAPS; t++) {
            int p = 0;
#pragma unroll
            for (int k = 0; k < CW; k++) {
                uint32_t v = __ldg(wp + t * CW + k);
                wr[t][k] = v;
                p += __popc(v);
            }
            Ct[t] = CIN - 2 * p;                       // contribution of a zero-halo tap
        }
    }
    __syncthreads();

    int       lsum = 0;
    long long lsq  = 0;

    for (int oh = 0; oh < TH; oh++) {
        const int gh = oh0 + oh;
        for (int ow = 0; ow < W; ow++) {
            int s = 0;
#pragma unroll
            for (int t = 0; t < TAPS; t++) {
                const int r = oh + t / 3;
                const int c = ow + t % 3;
                const uint4 xa = *reinterpret_cast<const uint4*>(&sx[r][c][0]);
                const uint4 xb = *reinterpret_cast<const uint4*>(&sx[r][c][4]);
                s += __popc(xa.x ^ wr[t][0]);
                s += __popc(xa.y ^ wr[t][1]);
                s += __popc(xa.z ^ wr[t][2]);
                s += __popc(xa.w ^ wr[t][3]);
                s += __popc(xb.x ^ wr[t][4]);
                s += __popc(xb.y ^ wr[t][5]);
                s += __popc(xb.z ^ wr[t][6]);
                s += __popc(xb.w ^ wr[t][7]);
            }
            int yv = CIN * TAPS - 2 * s;               // includes zero-halo taps

            // subtract contributions of out-of-bounds taps (uniform branch per block)
            int inv = 0;
            if (gh == 0)     inv |= 0x007;             // taps 0,1,2
            if (gh == H - 1) inv |= 0x1C0;             // taps 6,7,8
            if (ow == 0)     inv |= 0x049;             // taps 0,3,6
            if (ow == W - 1) inv |= 0x124;             // taps 2,5,8
            if (inv) {
#pragma unroll
                for (int t = 0; t < TAPS; t++)
                    if ((inv >> t) & 1) yv -= Ct[t];
            }

            g_y[(((size_t)n * H + gh) * W + ow) * COUT + oc] = (short)yv;  // NHWC: coalesced
            lsum += yv;
            lsq  += (long long)(yv * yv);
        }
    }
    atomicAdd(&g_sum[oc], lsum);
    atomicAdd(&g_sq[oc], (unsigned long long)lsq);
}

// -------- kernel 4: BN scale/shift from exact integer stats --------
__global__ void stats_kernel(const float* __restrict__ gamma,
                             const float* __restrict__ beta) {
    int c = threadIdx.x;
    const double cnt  = (double)NHW;
    double mean = (double)g_sum[c] / cnt;
    double ex2  = (double)(long long)g_sq[c] / cnt;
    double var  = ex2 - mean * mean;
    double inv  = 1.0 / sqrt(var + 1e-5);
    double sc   = (double)gamma[c] * inv;
    g_scale[c] = (float)sc;
    g_shift[c] = (float)((double)beta[c] - mean * sc);
}

// -------- kernel 5: BN apply + NHWC -> NCHW transpose --------
#define WT 28   // w-tile per block (2 tiles cover W=56)
__global__ void __launch_bounds__(256)
apply_kernel(float* __restrict__ out) {
    __shared__ float sy[WT * 257];                     // padded: conflict-free both phases (28.1 KB)

    const int wt = blockIdx.x;                         // 0..1
    const int h  = blockIdx.y;                         // 0..55
    const int n  = blockIdx.z;                         // 0..31
    const int tid = threadIdx.x;

    // load NHWC (coalesced over oc) and apply BN
    for (int idx = tid; idx < WT * COUT; idx += 256) {
        int lw = idx >> 8;                             // idx / 256
        int oc = idx & 255;
        int gw = wt * WT + lw;
        float yv = (float)g_y[(((size_t)n * H + h) * W + gw) * COUT + oc];
        sy[lw * 257 + oc] = yv * g_scale[oc] + g_shift[oc];
    }
    __syncthreads();

    // store NCHW (coalesced over w)
    for (int idx = tid; idx < WT * COUT; idx += 256) {
        int oc = idx / WT;
        int lw = idx - oc * WT;
        out[(((size_t)n * COUT + oc) * H + h) * W + wt * WT + lw] = sy[lw * 257 + oc];
    }
}

// -------- launch --------
extern "C" void kernel_launch(void* const* d_in, const int* in_sizes, int n_in,
                              void* d_out, int out_size) {
    const float* x     = (const float*)d_in[0];
    const float* w     = (const float*)d_in[1];
    const float* gamma = (const float*)d_in[2];
    const float* beta  = (const float*)d_in[3];
    float* out = (float*)d_out;

    pack_x_kernel<<<(NHW + 255) / 256, 256>>>(x);
    pack_w_kernel<<<(COUT * TAPS * CW + 255) / 256, 256>>>(w);

    dim3 cgrid(H / TH, NB);                            // (14, 32)
    conv_kernel<<<cgrid, 256>>>();

    stats_kernel<<<1, COUT>>>(gamma, beta);

    dim3 agrid(W / WT, H, NB);                         // (2, 56, 32)
    apply_kernel<<<agrid, 256>>>(out);
}